// round 3
// baseline (speedup 1.0000x reference)
#include <cuda_runtime.h>
#include <cuda_bf16.h>
#include <math.h>

// ---------------------------------------------------------------------------
// Transformer forward, 4 layers, fp32. B=4, L=1024, E=1024, H=16, d=64,
// MLP=4096. M_total = B*L = 4096.
//
// CRITICAL FIX vs rounds 1-2: __device__ scratch must be addressed via
// cudaGetSymbolAddress on the host. Passing the symbol directly hands kernels
// the HOST shadow address, which GB300's ATS silently dereferences (reads
// zeros, writes to host .bss) instead of faulting.
// ---------------------------------------------------------------------------

#define NUM_LAYERS 4
#define EMBED 1024
#define HEADS 16
#define HEAD_DIM 64
#define MLPDIM 4096
#define BATCH 4
#define SEQ 1024
#define MTOT (BATCH * SEQ)
#define EPS_LN 1e-6f

#define NSLAB ((size_t)MTOT * EMBED)          // 4 M floats per slab

// one scratch arena: x,q,k,v,u,a,h,z (8 slabs) + m (16 M floats)
__device__ float g_scratch[8 * NSLAB + (size_t)MTOT * MLPDIM];

// -------------------- block reductions (256 threads) -----------------------
__device__ __forceinline__ float block_sum256(float v, float* red) {
    #pragma unroll
    for (int o = 16; o; o >>= 1) v += __shfl_xor_sync(0xffffffffu, v, o);
    int t = threadIdx.x;
    if ((t & 31) == 0) red[t >> 5] = v;
    __syncthreads();
    float r = (t < 8) ? red[t] : 0.f;
    if (t < 32) {
        #pragma unroll
        for (int o = 4; o; o >>= 1) r += __shfl_xor_sync(0xffffffffu, r, o);
        if (t == 0) red[0] = r;
    }
    __syncthreads();
    r = red[0];
    __syncthreads();
    return r;
}

__device__ __forceinline__ float block_max256(float v, float* red) {
    #pragma unroll
    for (int o = 16; o; o >>= 1) v = fmaxf(v, __shfl_xor_sync(0xffffffffu, v, o));
    int t = threadIdx.x;
    if ((t & 31) == 0) red[t >> 5] = v;
    __syncthreads();
    float r = (t < 8) ? red[t] : -3.4e38f;
    if (t < 32) {
        #pragma unroll
        for (int o = 4; o; o >>= 1) r = fmaxf(r, __shfl_xor_sync(0xffffffffu, r, o));
        if (t == 0) red[0] = r;
    }
    __syncthreads();
    r = red[0];
    __syncthreads();
    return r;
}

// -------------------- SGEMM: C = alpha*(A@B + bias), optional relu ---------
// A [M,K] rm, B [K,N] rm, bias[N]. 128x128 tile, BK=16, 256 thr, 8x8/thread.
#define BM 128
#define BN 128
#define BKK 16

__global__ __launch_bounds__(256) void sgemm_bias(
    const float* __restrict__ A, const float* __restrict__ Bw,
    const float* __restrict__ bias, float* __restrict__ C,
    int M, int N, int K, float alpha, int relu)
{
    __shared__ float As[BKK][BM + 4];
    __shared__ float Bs[BKK][BN + 4];
    const int tid = threadIdx.x;
    const int m0 = blockIdx.y * BM;
    const int n0 = blockIdx.x * BN;
    const int tx = tid & 15;
    const int ty = tid >> 4;

    float acc[8][8] = {};

    for (int k0 = 0; k0 < K; k0 += BKK) {
        #pragma unroll
        for (int r = 0; r < 2; r++) {
            int f = tid + r * 256;
            int row = f >> 2;
            int kc = (f & 3) << 2;
            float4 a = *(const float4*)(A + (size_t)(m0 + row) * K + k0 + kc);
            As[kc + 0][row] = a.x; As[kc + 1][row] = a.y;
            As[kc + 2][row] = a.z; As[kc + 3][row] = a.w;
        }
        #pragma unroll
        for (int r = 0; r < 2; r++) {
            int f = tid + r * 256;
            int row = f >> 5;
            int c = (f & 31) << 2;
            *(float4*)&Bs[row][c] = *(const float4*)(Bw + (size_t)(k0 + row) * N + n0 + c);
        }
        __syncthreads();
        #pragma unroll
        for (int kk = 0; kk < BKK; kk++) {
            float a_reg[8], b_reg[8];
            #pragma unroll
            for (int i = 0; i < 8; i++) a_reg[i] = As[kk][ty * 8 + i];
            #pragma unroll
            for (int j = 0; j < 8; j++) b_reg[j] = Bs[kk][tx * 8 + j];
            #pragma unroll
            for (int i = 0; i < 8; i++)
                #pragma unroll
                for (int j = 0; j < 8; j++)
                    acc[i][j] = fmaf(a_reg[i], b_reg[j], acc[i][j]);
        }
        __syncthreads();
    }

    float bvals[8];
    #pragma unroll
    for (int j = 0; j < 8; j++) bvals[j] = bias[n0 + tx * 8 + j];

    #pragma unroll
    for (int i = 0; i < 8; i++) {
        size_t crow = (size_t)(m0 + ty * 8 + i) * N + n0 + tx * 8;
        #pragma unroll
        for (int j = 0; j < 8; j++) {
            float val = alpha * (acc[i][j] + bvals[j]);
            if (relu) val = fmaxf(val, 0.f);
            C[crow + j] = val;
        }
    }
}

// -------------------- fused attention: one block per (q row, b, h) ---------
__global__ __launch_bounds__(256) void attn_fused(
    const float* __restrict__ gq, const float* __restrict__ gk,
    const float* __restrict__ gv, float* __restrict__ gu)
{
    __shared__ float qrow[HEAD_DIM];
    __shared__ float P[SEQ];
    __shared__ float red[32];
    __shared__ float Uacc[4][HEAD_DIM];

    const int q  = blockIdx.x;
    const int bh = blockIdx.y;
    const int b  = bh >> 4;
    const int h  = bh & 15;
    const int t  = threadIdx.x;

    const float* qb = gq + ((size_t)b * SEQ + q) * EMBED + h * HEAD_DIM;
    const float* kb = gk + (size_t)b * SEQ * EMBED + h * HEAD_DIM;
    const float* vb = gv + (size_t)b * SEQ * EMBED + h * HEAD_DIM;

    if (t < 16) ((float4*)qrow)[t] = ((const float4*)qb)[t];
    __syncthreads();

    float s[4];
    #pragma unroll
    for (int j = 0; j < 4; j++) {
        const float* krow = kb + (size_t)(t + j * 256) * EMBED;
        float acc = 0.f;
        #pragma unroll
        for (int d4 = 0; d4 < 16; d4++) {
            float4 kv = ((const float4*)krow)[d4];
            acc = fmaf(qrow[d4 * 4 + 0], kv.x, acc);
            acc = fmaf(qrow[d4 * 4 + 1], kv.y, acc);
            acc = fmaf(qrow[d4 * 4 + 2], kv.z, acc);
            acc = fmaf(qrow[d4 * 4 + 3], kv.w, acc);
        }
        s[j] = acc;
    }

    float mx = fmaxf(fmaxf(s[0], s[1]), fmaxf(s[2], s[3]));
    mx = block_max256(mx, red);
    float sum = 0.f;
    #pragma unroll
    for (int j = 0; j < 4; j++) { s[j] = __expf(s[j] - mx); sum += s[j]; }
    sum = block_sum256(sum, red);
    float inv = 1.f / sum;
    #pragma unroll
    for (int j = 0; j < 4; j++) P[t + j * 256] = s[j] * inv;
    __syncthreads();

    const int d = t & 63;
    const int slice = t >> 6;
    float u = 0.f;
    const int kbeg = slice * 256;
    #pragma unroll 4
    for (int k = kbeg; k < kbeg + 256; k++)
        u = fmaf(P[k], vb[(size_t)k * EMBED + d], u);
    Uacc[slice][d] = u;
    __syncthreads();

    if (t < HEAD_DIM) {
        float r2 = Uacc[0][t] + Uacc[1][t] + Uacc[2][t] + Uacc[3][t];
        gu[((size_t)b * SEQ + q) * EMBED + h * HEAD_DIM + t] = r2;
    }
}

// -------------------- residual + layernorm ---------------------------------
__global__ __launch_bounds__(256) void ln_residual(
    const float* __restrict__ a, const float* __restrict__ res,
    const float* __restrict__ sc, const float* __restrict__ bi,
    float* __restrict__ out)
{
    __shared__ float red[32];
    const size_t row = blockIdx.x;
    const int t = threadIdx.x;
    float4 a4 = ((const float4*)(a + row * EMBED))[t];
    float4 r4 = ((const float4*)(res + row * EMBED))[t];
    float4 v;
    v.x = a4.x + r4.x; v.y = a4.y + r4.y; v.z = a4.z + r4.z; v.w = a4.w + r4.w;
    float s = v.x + v.y + v.z + v.w;
    s = block_sum256(s, red);
    float mean = s * (1.f / EMBED);
    v.x -= mean; v.y -= mean; v.z -= mean; v.w -= mean;
    float sq = v.x * v.x + v.y * v.y + v.z * v.z + v.w * v.w;
    sq = block_sum256(sq, red);
    float inv = rsqrtf(sq * (1.f / EMBED) + EPS_LN);
    float4 s4 = ((const float4*)sc)[t];
    float4 b4 = ((const float4*)bi)[t];
    float4 o;
    o.x = v.x * inv * s4.x + b4.x;
    o.y = v.y * inv * s4.y + b4.y;
    o.z = v.z * inv * s4.z + b4.z;
    o.w = v.w * inv * s4.w + b4.w;
    ((float4*)(out + row * EMBED))[t] = o;
}

// -------------------- input identification ---------------------------------
struct Inputs {
    const float *queries, *Wq, *bq, *Wk, *bk, *Wv, *bv, *Wo, *bo;
    const float *l1s, *l1b, *l2s, *l2b, *W1, *b1, *W2, *b2;
};

static void map_inputs(void* const* d_in, const int* in_sizes, Inputs* I)
{
    const int SZ_Q = MTOT * EMBED;                 // 4194304
    const int SZ_W = NUM_LAYERS * EMBED * MLPDIM;  // 16777216
    const int SZ_B1 = NUM_LAYERS * MLPDIM;         // 16384
    const int SZ_V = NUM_LAYERS * EMBED;           // 4096

    static const int dict_pat[17] = {SZ_Q,SZ_Q,SZ_V,SZ_Q,SZ_V,SZ_Q,SZ_V,SZ_Q,
                                     SZ_V,SZ_V,SZ_V,SZ_V,SZ_V,SZ_W,SZ_B1,SZ_W,SZ_V};
    static const int alpha_pat[17] = {SZ_W,SZ_W,SZ_Q,SZ_Q,SZ_Q,SZ_Q,SZ_B1,SZ_V,
                                      SZ_V,SZ_V,SZ_V,SZ_V,SZ_V,SZ_V,SZ_V,SZ_V,SZ_Q};
    bool is_dict = true, is_alpha = true;
    for (int i = 0; i < 17; i++) {
        if (in_sizes[i] != dict_pat[i])  is_dict = false;
        if (in_sizes[i] != alpha_pat[i]) is_alpha = false;
    }
    const float** p = (const float**)d_in;
    if (is_alpha) {
        I->W1 = p[0];  I->W2 = p[1];  I->Wk = p[2];  I->Wo = p[3];
        I->Wq = p[4];  I->Wv = p[5];  I->b1 = p[6];  I->b2 = p[7];
        I->bk = p[8];  I->bo = p[9];  I->bq = p[10]; I->bv = p[11];
        I->l1b = p[12];I->l1s = p[13];I->l2b = p[14];I->l2s = p[15];
        I->queries = p[16];
    } else if (is_dict) {
        I->queries = p[0];  I->Wq = p[1];  I->bq = p[2];  I->Wk = p[3];
        I->bk = p[4];       I->Wv = p[5];  I->bv = p[6];  I->Wo = p[7];
        I->bo = p[8];       I->l1s = p[9]; I->l1b = p[10];I->l2s = p[11];
        I->l2b = p[12];     I->W1 = p[13]; I->b1 = p[14]; I->W2 = p[15];
        I->b2 = p[16];
    } else {
        // size-class fallback, dict appearance order within classes
        const float* cq[8]; int nq = 0;
        const float* cw[4]; int nw = 0;
        const float* cv[12]; int nv = 0;
        const float* cb1 = 0;
        for (int i = 0; i < 17; i++) {
            if (in_sizes[i] == SZ_Q && nq < 8) cq[nq++] = p[i];
            else if (in_sizes[i] == SZ_W && nw < 4) cw[nw++] = p[i];
            else if (in_sizes[i] == SZ_B1) cb1 = p[i];
            else if (nv < 12) cv[nv++] = p[i];
        }
        I->queries = cq[0]; I->Wq = cq[1]; I->Wk = cq[2]; I->Wv = cq[3]; I->Wo = cq[4];
        I->W1 = cw[0]; I->W2 = cw[1]; I->b1 = cb1;
        I->bq = cv[0]; I->bk = cv[1]; I->bv = cv[2]; I->bo = cv[3];
        I->l1s = cv[4]; I->l1b = cv[5]; I->l2s = cv[6]; I->l2b = cv[7]; I->b2 = cv[8];
    }
}

// -------------------- host orchestration -----------------------------------
extern "C" void kernel_launch(void* const* d_in, const int* in_sizes, int n_in,
                              void* d_out, int out_size)
{
    Inputs I;
    map_inputs(d_in, in_sizes, &I);
    float* out = (float*)d_out;

    // Resolve the REAL device address of the scratch arena (capture-safe,
    // deterministic, no allocation).
    void* base_v = 0;
    cudaGetSymbolAddress(&base_v, g_scratch);
    float* base = (float*)base_v;
    float* x = base + 0 * NSLAB;
    float* q = base + 1 * NSLAB;
    float* k = base + 2 * NSLAB;
    float* v = base + 3 * NSLAB;
    float* u = base + 4 * NSLAB;
    float* a = base + 5 * NSLAB;
    float* h = base + 6 * NSLAB;
    float* z = base + 7 * NSLAB;
    float* m = base + 8 * NSLAB;

    cudaMemcpyAsync(x, I.queries, NSLAB * sizeof(float), cudaMemcpyDeviceToDevice, 0);

    const float qscale = 1.f / sqrtf((float)HEAD_DIM);

    for (int l = 0; l < NUM_LAYERS; l++) {
        const float* Wq_l = I.Wq + (size_t)l * EMBED * EMBED;
        const float* Wk_l = I.Wk + (size_t)l * EMBED * EMBED;
        const float* Wv_l = I.Wv + (size_t)l * EMBED * EMBED;
        const float* Wo_l = I.Wo + (size_t)l * EMBED * EMBED;
        const float* W1_l = I.W1 + (size_t)l * EMBED * MLPDIM;
        const float* W2_l = I.W2 + (size_t)l * MLPDIM * EMBED;
        const float* bq_l = I.bq + (size_t)l * EMBED;
        const float* bk_l = I.bk + (size_t)l * EMBED;
        const float* bv_l = I.bv + (size_t)l * EMBED;
        const float* bo_l = I.bo + (size_t)l * EMBED;
        const float* b1_l = I.b1 + (size_t)l * MLPDIM;
        const float* b2_l = I.b2 + (size_t)l * EMBED;
        const float* l1s = I.l1s + (size_t)l * EMBED;
        const float* l1b = I.l1b + (size_t)l * EMBED;
        const float* l2s = I.l2s + (size_t)l * EMBED;
        const float* l2b = I.l2b + (size_t)l * EMBED;

        dim3 gE(EMBED / BN, MTOT / BM);            // (8, 32)
        sgemm_bias<<<gE, 256>>>(x, Wq_l, bq_l, q, MTOT, EMBED, EMBED, qscale, 0);
        sgemm_bias<<<gE, 256>>>(x, Wk_l, bk_l, k, MTOT, EMBED, EMBED, 1.f, 0);
        sgemm_bias<<<gE, 256>>>(x, Wv_l, bv_l, v, MTOT, EMBED, EMBED, 1.f, 0);

        attn_fused<<<dim3(SEQ, BATCH * HEADS), 256>>>(q, k, v, u);

        sgemm_bias<<<gE, 256>>>(u, Wo_l, bo_l, a, MTOT, EMBED, EMBED, 1.f, 0);
        ln_residual<<<MTOT, 256>>>(a, x, l1s, l1b, h);

        sgemm_bias<<<dim3(MLPDIM / BN, MTOT / BM), 256>>>(
            h, W1_l, b1_l, m, MTOT, MLPDIM, EMBED, 1.f, 1);
        sgemm_bias<<<dim3(EMBED / BN, MTOT / BM), 256>>>(
            m, W2_l, b2_l, z, MTOT, EMBED, MLPDIM, 1.f, 0);
        ln_residual<<<MTOT, 256>>>(z, h, l2s, l2b, x);
    }

    cudaMemcpyAsync(out, x, NSLAB * sizeof(float), cudaMemcpyDeviceToDevice, 0);
}

// round 4
// speedup vs baseline: 1.1830x; 1.1830x over previous
#include <cuda_runtime.h>
#include <cuda_bf16.h>
#include <math.h>
#include <stdint.h>

// ---------------------------------------------------------------------------
// Transformer forward, 4 layers. B=4, L=1024, E=1024, H=16, d=64, MLP=4096.
// GEMMs on tensor cores: bf16 hi/lo split (3xBF16) mma.sync, fp32 accumulate.
// ---------------------------------------------------------------------------

#define NUM_LAYERS 4
#define EMBED 1024
#define HEADS 16
#define HEAD_DIM 64
#define MLPDIM 4096
#define BATCH 4
#define SEQ 1024
#define MTOT (BATCH * SEQ)
#define EPS_LN 1e-6f

#define NSLAB ((size_t)MTOT * EMBED)            // 4 M floats

// fp32 scratch: x,q,k,v,u,a,h,z (8 slabs) + m (16 M)
__device__ float g_f[8 * NSLAB + (size_t)MTOT * MLPDIM];

// bf16 weight splits (transposed to [N][K] per layer)
#define WSQ ((size_t)NUM_LAYERS * EMBED * EMBED)     // 4,194,304
#define WSM ((size_t)NUM_LAYERS * EMBED * MLPDIM)    // 16,777,216
__device__ __nv_bfloat16 g_wq_h[WSQ], g_wq_l[WSQ];
__device__ __nv_bfloat16 g_wk_h[WSQ], g_wk_l[WSQ];
__device__ __nv_bfloat16 g_wv_h[WSQ], g_wv_l[WSQ];
__device__ __nv_bfloat16 g_wo_h[WSQ], g_wo_l[WSQ];
__device__ __nv_bfloat16 g_w1_h[WSM], g_w1_l[WSM];
__device__ __nv_bfloat16 g_w2_h[WSM], g_w2_l[WSM];
// activation splits (max 16.8M elements for m)
__device__ __nv_bfloat16 g_ah[(size_t)MTOT * MLPDIM];
__device__ __nv_bfloat16 g_al[(size_t)MTOT * MLPDIM];

// -------------------- block reductions (256 threads) -----------------------
__device__ __forceinline__ float block_sum256(float v, float* red) {
    #pragma unroll
    for (int o = 16; o; o >>= 1) v += __shfl_xor_sync(0xffffffffu, v, o);
    int t = threadIdx.x;
    if ((t & 31) == 0) red[t >> 5] = v;
    __syncthreads();
    float r = (t < 8) ? red[t] : 0.f;
    if (t < 32) {
        #pragma unroll
        for (int o = 4; o; o >>= 1) r += __shfl_xor_sync(0xffffffffu, r, o);
        if (t == 0) red[0] = r;
    }
    __syncthreads();
    r = red[0];
    __syncthreads();
    return r;
}

__device__ __forceinline__ float block_max256(float v, float* red) {
    #pragma unroll
    for (int o = 16; o; o >>= 1) v = fmaxf(v, __shfl_xor_sync(0xffffffffu, v, o));
    int t = threadIdx.x;
    if ((t & 31) == 0) red[t >> 5] = v;
    __syncthreads();
    float r = (t < 8) ? red[t] : -3.4e38f;
    if (t < 32) {
        #pragma unroll
        for (int o = 4; o; o >>= 1) r = fmaxf(r, __shfl_xor_sync(0xffffffffu, r, o));
        if (t == 0) red[0] = r;
    }
    __syncthreads();
    r = red[0];
    __syncthreads();
    return r;
}

// -------------------- weight split + transpose -----------------------------
// in: W[L][K][N] fp32 ; out: Th/Tl[L][N][K] bf16 (hi, residual-lo)
__global__ __launch_bounds__(256) void wsplit_t(
    const float* __restrict__ W, __nv_bfloat16* __restrict__ Th,
    __nv_bfloat16* __restrict__ Tl, int K, int N)
{
    __shared__ float tile[32][33];
    const int l = blockIdx.z;
    const float* Wl = W + (size_t)l * K * N;
    __nv_bfloat16* Thl = Th + (size_t)l * K * N;
    __nv_bfloat16* Tll = Tl + (size_t)l * K * N;
    const int n0 = blockIdx.x * 32, k0 = blockIdx.y * 32;
    const int tx = threadIdx.x & 31, ty = threadIdx.x >> 5;   // 32x8
    #pragma unroll
    for (int j = 0; j < 32; j += 8)
        tile[ty + j][tx] = Wl[(size_t)(k0 + ty + j) * N + n0 + tx];
    __syncthreads();
    #pragma unroll
    for (int j = 0; j < 32; j += 8) {
        float v = tile[tx][ty + j];
        __nv_bfloat16 h = __float2bfloat16(v);
        float lo = v - __bfloat162float(h);
        size_t o = (size_t)(n0 + ty + j) * K + k0 + tx;
        Thl[o] = h;
        Tll[o] = __float2bfloat16(lo);
    }
}

// -------------------- activation split -------------------------------------
__global__ __launch_bounds__(256) void asplit(
    const float* __restrict__ x, __nv_bfloat16* __restrict__ hh,
    __nv_bfloat16* __restrict__ ll)
{
    size_t i = ((size_t)blockIdx.x * 256 + threadIdx.x) * 4;
    float4 v = *(const float4*)(x + i);
    __nv_bfloat16 h0 = __float2bfloat16(v.x);
    __nv_bfloat16 h1 = __float2bfloat16(v.y);
    __nv_bfloat16 h2 = __float2bfloat16(v.z);
    __nv_bfloat16 h3 = __float2bfloat16(v.w);
    __nv_bfloat162* ph = (__nv_bfloat162*)(hh + i);
    ph[0] = __nv_bfloat162(h0, h1);
    ph[1] = __nv_bfloat162(h2, h3);
    __nv_bfloat162* pl = (__nv_bfloat162*)(ll + i);
    pl[0] = __nv_bfloat162(__float2bfloat16(v.x - __bfloat162float(h0)),
                           __float2bfloat16(v.y - __bfloat162float(h1)));
    pl[1] = __nv_bfloat162(__float2bfloat16(v.z - __bfloat162float(h2)),
                           __float2bfloat16(v.w - __bfloat162float(h3)));
}

// -------------------- 3xBF16 tensor-core GEMM ------------------------------
// C[M][N] = alpha*(A@B + bias), A[M][K] rm (hi/lo bf16), Bt[N][K] rm (hi/lo).
// Tile 128x128, BK=32. 8 warps: 4(M)x2(N), warp tile 32x64. mma m16n8k16.
#define SMS 40   // smem row stride in bf16 elements (80B: 16B-aligned, conflict-free)

__device__ __forceinline__ void mma16816(float* c, const uint32_t* a, const uint32_t* b)
{
    asm volatile(
        "mma.sync.aligned.m16n8k16.row.col.f32.bf16.bf16.f32 "
        "{%0,%1,%2,%3}, {%4,%5,%6,%7}, {%8,%9}, {%0,%1,%2,%3};"
        : "+f"(c[0]), "+f"(c[1]), "+f"(c[2]), "+f"(c[3])
        : "r"(a[0]), "r"(a[1]), "r"(a[2]), "r"(a[3]), "r"(b[0]), "r"(b[1]));
}

__global__ __launch_bounds__(256) void gemm3x(
    const __nv_bfloat16* __restrict__ Ah, const __nv_bfloat16* __restrict__ Al,
    const __nv_bfloat16* __restrict__ Bth, const __nv_bfloat16* __restrict__ Btl,
    const float* __restrict__ bias, float* __restrict__ C,
    int M, int N, int K, float alpha, int relu)
{
    __shared__ __align__(16) __nv_bfloat16 As_h[128 * SMS];
    __shared__ __align__(16) __nv_bfloat16 As_l[128 * SMS];
    __shared__ __align__(16) __nv_bfloat16 Bs_h[128 * SMS];
    __shared__ __align__(16) __nv_bfloat16 Bs_l[128 * SMS];

    const int tid = threadIdx.x;
    const int warp = tid >> 5;
    const int lane = tid & 31;
    const int g = lane >> 2;          // group 0..7
    const int t2 = (lane & 3) * 2;    // 0,2,4,6
    const int wm = warp >> 1;         // 0..3 -> m offset 32*wm
    const int wn = warp & 1;          // 0..1 -> n offset 64*wn
    const int m0 = blockIdx.y * 128;
    const int n0 = blockIdx.x * 128;

    float acc[2][8][4];
    #pragma unroll
    for (int i = 0; i < 2; i++)
        #pragma unroll
        for (int j = 0; j < 8; j++)
            #pragma unroll
            for (int c = 0; c < 4; c++) acc[i][j][c] = 0.f;

    for (int k0 = 0; k0 < K; k0 += 32) {
        // load 128x32 tiles of A(hi,lo) and Bt(hi,lo): 512 uint4 each pair
        #pragma unroll
        for (int r = 0; r < 2; r++) {
            int c = tid + r * 256;           // 0..511
            int row = c >> 2;
            int qt = (c & 3) * 8;            // element offset
            size_t ga = (size_t)(m0 + row) * K + k0 + qt;
            size_t gb = (size_t)(n0 + row) * K + k0 + qt;
            *(uint4*)&As_h[row * SMS + qt] = *(const uint4*)&Ah[ga];
            *(uint4*)&As_l[row * SMS + qt] = *(const uint4*)&Al[ga];
            *(uint4*)&Bs_h[row * SMS + qt] = *(const uint4*)&Bth[gb];
            *(uint4*)&Bs_l[row * SMS + qt] = *(const uint4*)&Btl[gb];
        }
        __syncthreads();

        #pragma unroll
        for (int kk = 0; kk < 32; kk += 16) {
            // B fragments for 8 n-steps
            uint32_t bh[8][2], bl[8][2];
            #pragma unroll
            for (int ns = 0; ns < 8; ns++) {
                int n = wn * 64 + ns * 8 + g;
                bh[ns][0] = *(const uint32_t*)&Bs_h[n * SMS + kk + t2];
                bh[ns][1] = *(const uint32_t*)&Bs_h[n * SMS + kk + t2 + 8];
                bl[ns][0] = *(const uint32_t*)&Bs_l[n * SMS + kk + t2];
                bl[ns][1] = *(const uint32_t*)&Bs_l[n * SMS + kk + t2 + 8];
            }
            #pragma unroll
            for (int ms = 0; ms < 2; ms++) {
                int r0 = wm * 32 + ms * 16 + g;
                uint32_t ah[4], al[4];
                ah[0] = *(const uint32_t*)&As_h[r0 * SMS + kk + t2];
                ah[1] = *(const uint32_t*)&As_h[(r0 + 8) * SMS + kk + t2];
                ah[2] = *(const uint32_t*)&As_h[r0 * SMS + kk + t2 + 8];
                ah[3] = *(const uint32_t*)&As_h[(r0 + 8) * SMS + kk + t2 + 8];
                al[0] = *(const uint32_t*)&As_l[r0 * SMS + kk + t2];
                al[1] = *(const uint32_t*)&As_l[(r0 + 8) * SMS + kk + t2];
                al[2] = *(const uint32_t*)&As_l[r0 * SMS + kk + t2 + 8];
                al[3] = *(const uint32_t*)&As_l[(r0 + 8) * SMS + kk + t2 + 8];
                #pragma unroll
                for (int ns = 0; ns < 8; ns++) {
                    mma16816(acc[ms][ns], ah, bh[ns]);   // hi*hi
                    mma16816(acc[ms][ns], ah, bl[ns]);   // hi*lo
                    mma16816(acc[ms][ns], al, bh[ns]);   // lo*hi
                }
            }
        }
        __syncthreads();
    }

    // epilogue
    #pragma unroll
    for (int ms = 0; ms < 2; ms++) {
        #pragma unroll
        for (int ns = 0; ns < 8; ns++) {
            int row0 = m0 + wm * 32 + ms * 16 + g;
            int col  = n0 + wn * 64 + ns * 8 + t2;
            float b0 = bias[col], b1 = bias[col + 1];
            float v0 = alpha * (acc[ms][ns][0] + b0);
            float v1 = alpha * (acc[ms][ns][1] + b1);
            float v2 = alpha * (acc[ms][ns][2] + b0);
            float v3 = alpha * (acc[ms][ns][3] + b1);
            if (relu) {
                v0 = fmaxf(v0, 0.f); v1 = fmaxf(v1, 0.f);
                v2 = fmaxf(v2, 0.f); v3 = fmaxf(v3, 0.f);
            }
            *(float2*)&C[(size_t)row0 * N + col] = make_float2(v0, v1);
            *(float2*)&C[(size_t)(row0 + 8) * N + col] = make_float2(v2, v3);
        }
    }
}

// -------------------- fused attention: one block per (q row, b, h) ---------
__global__ __launch_bounds__(256) void attn_fused(
    const float* __restrict__ gq, const float* __restrict__ gk,
    const float* __restrict__ gv, float* __restrict__ gu)
{
    __shared__ float qrow[HEAD_DIM];
    __shared__ float P[SEQ];
    __shared__ float red[32];
    __shared__ float Uacc[4][HEAD_DIM];

    const int q  = blockIdx.x;
    const int bh = blockIdx.y;
    const int b  = bh >> 4;
    const int h  = bh & 15;
    const int t  = threadIdx.x;

    const float* qb = gq + ((size_t)b * SEQ + q) * EMBED + h * HEAD_DIM;
    const float* kb = gk + (size_t)b * SEQ * EMBED + h * HEAD_DIM;
    const float* vb = gv + (size_t)b * SEQ * EMBED + h * HEAD_DIM;

    if (t < 16) ((float4*)qrow)[t] = ((const float4*)qb)[t];
    __syncthreads();

    float s[4];
    #pragma unroll
    for (int j = 0; j < 4; j++) {
        const float* krow = kb + (size_t)(t + j * 256) * EMBED;
        float acc = 0.f;
        #pragma unroll
        for (int d4 = 0; d4 < 16; d4++) {
            float4 kv = ((const float4*)krow)[d4];
            acc = fmaf(qrow[d4 * 4 + 0], kv.x, acc);
            acc = fmaf(qrow[d4 * 4 + 1], kv.y, acc);
            acc = fmaf(qrow[d4 * 4 + 2], kv.z, acc);
            acc = fmaf(qrow[d4 * 4 + 3], kv.w, acc);
        }
        s[j] = acc;
    }

    float mx = fmaxf(fmaxf(s[0], s[1]), fmaxf(s[2], s[3]));
    mx = block_max256(mx, red);
    float sum = 0.f;
    #pragma unroll
    for (int j = 0; j < 4; j++) { s[j] = __expf(s[j] - mx); sum += s[j]; }
    sum = block_sum256(sum, red);
    float inv = 1.f / sum;
    #pragma unroll
    for (int j = 0; j < 4; j++) P[t + j * 256] = s[j] * inv;
    __syncthreads();

    const int d = t & 63;
    const int slice = t >> 6;
    float u = 0.f;
    const int kbeg = slice * 256;
    #pragma unroll 4
    for (int k = kbeg; k < kbeg + 256; k++)
        u = fmaf(P[k], vb[(size_t)k * EMBED + d], u);
    Uacc[slice][d] = u;
    __syncthreads();

    if (t < HEAD_DIM) {
        float r2 = Uacc[0][t] + Uacc[1][t] + Uacc[2][t] + Uacc[3][t];
        gu[((size_t)b * SEQ + q) * EMBED + h * HEAD_DIM + t] = r2;
    }
}

// -------------------- residual + layernorm ---------------------------------
__global__ __launch_bounds__(256) void ln_residual(
    const float* __restrict__ a, const float* __restrict__ res,
    const float* __restrict__ sc, const float* __restrict__ bi,
    float* __restrict__ out)
{
    __shared__ float red[32];
    const size_t row = blockIdx.x;
    const int t = threadIdx.x;
    float4 a4 = ((const float4*)(a + row * EMBED))[t];
    float4 r4 = ((const float4*)(res + row * EMBED))[t];
    float4 v;
    v.x = a4.x + r4.x; v.y = a4.y + r4.y; v.z = a4.z + r4.z; v.w = a4.w + r4.w;
    float s = v.x + v.y + v.z + v.w;
    s = block_sum256(s, red);
    float mean = s * (1.f / EMBED);
    v.x -= mean; v.y -= mean; v.z -= mean; v.w -= mean;
    float sq = v.x * v.x + v.y * v.y + v.z * v.z + v.w * v.w;
    sq = block_sum256(sq, red);
    float inv = rsqrtf(sq * (1.f / EMBED) + EPS_LN);
    float4 s4 = ((const float4*)sc)[t];
    float4 b4 = ((const float4*)bi)[t];
    float4 o;
    o.x = v.x * inv * s4.x + b4.x;
    o.y = v.y * inv * s4.y + b4.y;
    o.z = v.z * inv * s4.z + b4.z;
    o.w = v.w * inv * s4.w + b4.w;
    ((float4*)(out + row * EMBED))[t] = o;
}

// -------------------- input identification ---------------------------------
struct Inputs {
    const float *queries, *Wq, *bq, *Wk, *bk, *Wv, *bv, *Wo, *bo;
    const float *l1s, *l1b, *l2s, *l2b, *W1, *b1, *W2, *b2;
};

static void map_inputs(void* const* d_in, const int* in_sizes, Inputs* I)
{
    const int SZ_Q = MTOT * EMBED;
    const int SZ_W = NUM_LAYERS * EMBED * MLPDIM;
    const int SZ_B1 = NUM_LAYERS * MLPDIM;
    const int SZ_V = NUM_LAYERS * EMBED;

    static const int dict_pat[17] = {SZ_Q,SZ_Q,SZ_V,SZ_Q,SZ_V,SZ_Q,SZ_V,SZ_Q,
                                     SZ_V,SZ_V,SZ_V,SZ_V,SZ_V,SZ_W,SZ_B1,SZ_W,SZ_V};
    static const int alpha_pat[17] = {SZ_W,SZ_W,SZ_Q,SZ_Q,SZ_Q,SZ_Q,SZ_B1,SZ_V,
                                      SZ_V,SZ_V,SZ_V,SZ_V,SZ_V,SZ_V,SZ_V,SZ_V,SZ_Q};
    bool is_dict = true, is_alpha = true;
    for (int i = 0; i < 17; i++) {
        if (in_sizes[i] != dict_pat[i])  is_dict = false;
        if (in_sizes[i] != alpha_pat[i]) is_alpha = false;
    }
    const float** p = (const float**)d_in;
    if (is_alpha) {
        I->W1 = p[0];  I->W2 = p[1];  I->Wk = p[2];  I->Wo = p[3];
        I->Wq = p[4];  I->Wv = p[5];  I->b1 = p[6];  I->b2 = p[7];
        I->bk = p[8];  I->bo = p[9];  I->bq = p[10]; I->bv = p[11];
        I->l1b = p[12];I->l1s = p[13];I->l2b = p[14];I->l2s = p[15];
        I->queries = p[16];
    } else if (is_dict) {
        I->queries = p[0];  I->Wq = p[1];  I->bq = p[2];  I->Wk = p[3];
        I->bk = p[4];       I->Wv = p[5];  I->bv = p[6];  I->Wo = p[7];
        I->bo = p[8];       I->l1s = p[9]; I->l1b = p[10];I->l2s = p[11];
        I->l2b = p[12];     I->W1 = p[13]; I->b1 = p[14]; I->W2 = p[15];
        I->b2 = p[16];
    } else {
        const float* cq[8]; int nq = 0;
        const float* cw[4]; int nw = 0;
        const float* cv[12]; int nv = 0;
        const float* cb1 = 0;
        for (int i = 0; i < 17; i++) {
            if (in_sizes[i] == SZ_Q && nq < 8) cq[nq++] = p[i];
            else if (in_sizes[i] == SZ_W && nw < 4) cw[nw++] = p[i];
            else if (in_sizes[i] == SZ_B1) cb1 = p[i];
            else if (nv < 12) cv[nv++] = p[i];
        }
        I->queries = cq[0]; I->Wq = cq[1]; I->Wk = cq[2]; I->Wv = cq[3]; I->Wo = cq[4];
        I->W1 = cw[0]; I->W2 = cw[1]; I->b1 = cb1;
        I->bq = cv[0]; I->bk = cv[1]; I->bv = cv[2]; I->bo = cv[3];
        I->l1s = cv[4]; I->l1b = cv[5]; I->l2s = cv[6]; I->l2b = cv[7]; I->b2 = cv[8];
    }
}

// -------------------- host orchestration -----------------------------------
static float* sym_addr_f(const void* sym) {
    void* pv = 0;
    cudaGetSymbolAddress(&pv, sym);
    return (float*)pv;
}
static __nv_bfloat16* sym_addr_b(const void* sym) {
    void* pv = 0;
    cudaGetSymbolAddress(&pv, sym);
    return (__nv_bfloat16*)pv;
}

extern "C" void kernel_launch(void* const* d_in, const int* in_sizes, int n_in,
                              void* d_out, int out_size)
{
    Inputs I;
    map_inputs(d_in, in_sizes, &I);
    float* out = (float*)d_out;

    float* fbase = sym_addr_f(g_f);
    float* x = fbase + 0 * NSLAB;
    float* q = fbase + 1 * NSLAB;
    float* k = fbase + 2 * NSLAB;
    float* v = fbase + 3 * NSLAB;
    float* u = fbase + 4 * NSLAB;
    float* a = fbase + 5 * NSLAB;
    float* h = fbase + 6 * NSLAB;
    float* z = fbase + 7 * NSLAB;
    float* m = fbase + 8 * NSLAB;

    __nv_bfloat16 *wq_h = sym_addr_b(g_wq_h), *wq_l = sym_addr_b(g_wq_l);
    __nv_bfloat16 *wk_h = sym_addr_b(g_wk_h), *wk_l = sym_addr_b(g_wk_l);
    __nv_bfloat16 *wv_h = sym_addr_b(g_wv_h), *wv_l = sym_addr_b(g_wv_l);
    __nv_bfloat16 *wo_h = sym_addr_b(g_wo_h), *wo_l = sym_addr_b(g_wo_l);
    __nv_bfloat16 *w1_h = sym_addr_b(g_w1_h), *w1_l = sym_addr_b(g_w1_l);
    __nv_bfloat16 *w2_h = sym_addr_b(g_w2_h), *w2_l = sym_addr_b(g_w2_l);
    __nv_bfloat16 *ah = sym_addr_b(g_ah), *al = sym_addr_b(g_al);

    // weight prep: split + transpose to [N][K] bf16 hi/lo
    dim3 tgrid_q(EMBED / 32, EMBED / 32, NUM_LAYERS);
    wsplit_t<<<tgrid_q, 256>>>(I.Wq, wq_h, wq_l, EMBED, EMBED);
    wsplit_t<<<tgrid_q, 256>>>(I.Wk, wk_h, wk_l, EMBED, EMBED);
    wsplit_t<<<tgrid_q, 256>>>(I.Wv, wv_h, wv_l, EMBED, EMBED);
    wsplit_t<<<tgrid_q, 256>>>(I.Wo, wo_h, wo_l, EMBED, EMBED);
    wsplit_t<<<dim3(MLPDIM / 32, EMBED / 32, NUM_LAYERS), 256>>>(
        I.W1, w1_h, w1_l, EMBED, MLPDIM);
    wsplit_t<<<dim3(EMBED / 32, MLPDIM / 32, NUM_LAYERS), 256>>>(
        I.W2, w2_h, w2_l, MLPDIM, EMBED);

    cudaMemcpyAsync(x, I.queries, NSLAB * sizeof(float), cudaMemcpyDeviceToDevice, 0);

    const float qscale = 1.f / sqrtf((float)HEAD_DIM);
    const int AS_E = (int)(NSLAB / 1024);              // 4096 blocks for 4M elems
    const int AS_M = (int)((size_t)MTOT * MLPDIM / 1024);

    for (int l = 0; l < NUM_LAYERS; l++) {
        size_t woq = (size_t)l * EMBED * EMBED;
        size_t wom = (size_t)l * EMBED * MLPDIM;
        const float* bq_l = I.bq + (size_t)l * EMBED;
        const float* bk_l = I.bk + (size_t)l * EMBED;
        const float* bv_l = I.bv + (size_t)l * EMBED;
        const float* bo_l = I.bo + (size_t)l * EMBED;
        const float* b1_l = I.b1 + (size_t)l * MLPDIM;
        const float* b2_l = I.b2 + (size_t)l * EMBED;
        const float* l1s = I.l1s + (size_t)l * EMBED;
        const float* l1b = I.l1b + (size_t)l * EMBED;
        const float* l2s = I.l2s + (size_t)l * EMBED;
        const float* l2b = I.l2b + (size_t)l * EMBED;

        dim3 gE(EMBED / 128, MTOT / 128);              // (8, 32)

        asplit<<<AS_E, 256>>>(x, ah, al);
        gemm3x<<<gE, 256>>>(ah, al, wq_h + woq, wq_l + woq, bq_l, q,
                            MTOT, EMBED, EMBED, qscale, 0);
        gemm3x<<<gE, 256>>>(ah, al, wk_h + woq, wk_l + woq, bk_l, k,
                            MTOT, EMBED, EMBED, 1.f, 0);
        gemm3x<<<gE, 256>>>(ah, al, wv_h + woq, wv_l + woq, bv_l, v,
                            MTOT, EMBED, EMBED, 1.f, 0);

        attn_fused<<<dim3(SEQ, BATCH * HEADS), 256>>>(q, k, v, u);

        asplit<<<AS_E, 256>>>(u, ah, al);
        gemm3x<<<gE, 256>>>(ah, al, wo_h + woq, wo_l + woq, bo_l, a,
                            MTOT, EMBED, EMBED, 1.f, 0);
        ln_residual<<<MTOT, 256>>>(a, x, l1s, l1b, h);

        asplit<<<AS_E, 256>>>(h, ah, al);
        gemm3x<<<dim3(MLPDIM / 128, MTOT / 128), 256>>>(
            ah, al, w1_h + wom, w1_l + wom, b1_l, m,
            MTOT, MLPDIM, EMBED, 1.f, 1);

        asplit<<<AS_M, 256>>>(m, ah, al);
        gemm3x<<<gE, 256>>>(ah, al, w2_h + wom, w2_l + wom, b2_l, z,
                            MTOT, EMBED, MLPDIM, 1.f, 0);
        ln_residual<<<MTOT, 256>>>(z, h, l2s, l2b, x);
    }

    cudaMemcpyAsync(out, x, NSLAB * sizeof(float), cudaMemcpyDeviceToDevice, 0);
}

// round 7
// speedup vs baseline: 1.4064x; 1.1888x over previous
#include <cuda_runtime.h>
#include <cuda_bf16.h>
#include <math.h>
#include <stdint.h>

// ---------------------------------------------------------------------------
// Transformer forward, 4 layers. B=4, L=1024, E=1024, H=16, d=64, MLP=4096.
// GEMMs: tcgen05 bf16 SS mma (3xBF16 hi/lo split) when the arch-specific
// cubin is loaded; mma.sync HMMA fallback otherwise. Host discriminates via
// cudaFuncGetAttributes (empty stub vs real body register counts).
// ---------------------------------------------------------------------------

#if (defined(__CUDA_ARCH_FEAT_SM103_ALL) || defined(__CUDA_ARCH_FEAT_SM100_ALL) || \
     defined(__CUDA_ARCH_FEAT_SM101_ALL) || \
     (defined(__CUDA_ARCH_SPECIFIC__) && (__CUDA_ARCH_SPECIFIC__ >= 1000)))
#define HAS_TCGEN05 1
#else
#define HAS_TCGEN05 0
#endif

#define NUM_LAYERS 4
#define EMBED 1024
#define HEADS 16
#define HEAD_DIM 64
#define MLPDIM 4096
#define BATCH 4
#define SEQ 1024
#define MTOT (BATCH * SEQ)
#define EPS_LN 1e-6f

#define NSLAB ((size_t)MTOT * EMBED)            // 4 M floats

// fp32 scratch: x,q,k,v,u,a,h,z (8 slabs) + m (16 M)
__device__ float g_f[8 * NSLAB + (size_t)MTOT * MLPDIM];

// bf16 weight splits (transposed to [N][K] per layer), 16B-aligned for cp.async
#define WSQ ((size_t)NUM_LAYERS * EMBED * EMBED)
#define WSM ((size_t)NUM_LAYERS * EMBED * MLPDIM)
__device__ __align__(16) __nv_bfloat16 g_wq_h[WSQ], g_wq_l[WSQ];
__device__ __align__(16) __nv_bfloat16 g_wk_h[WSQ], g_wk_l[WSQ];
__device__ __align__(16) __nv_bfloat16 g_wv_h[WSQ], g_wv_l[WSQ];
__device__ __align__(16) __nv_bfloat16 g_wo_h[WSQ], g_wo_l[WSQ];
__device__ __align__(16) __nv_bfloat16 g_w1_h[WSM], g_w1_l[WSM];
__device__ __align__(16) __nv_bfloat16 g_w2_h[WSM], g_w2_l[WSM];
__device__ __align__(16) __nv_bfloat16 g_ah[(size_t)MTOT * MLPDIM];
__device__ __align__(16) __nv_bfloat16 g_al[(size_t)MTOT * MLPDIM];

// -------------------- tcgen05 GEMM -----------------------------------------
// C[4096][N] = alpha*(A@Bt^T + bias), A hi/lo [4096][K] bf16, Bt hi/lo [N][K].
// CTA tile 128x256, BK=64 (one SW128 row), 2-stage cp.async ring, 128 threads.
#define GT_M 128
#define GT_N 256
#define STAGE_A (GT_M * 128)                       // 16 KB per A tile
#define STAGE_B (GT_N * 128)                       // 32 KB per B tile
#define STAGE_BYTES (2 * STAGE_A + 2 * STAGE_B)    // 96 KB
#define GEMM_SMEM (1024 + 2 * STAGE_BYTES)         // 197632 B

#if HAS_TCGEN05
__device__ __forceinline__ uint32_t s2u(const void* p) {
    uint32_t a;
    asm("{ .reg .u64 t; cvta.to.shared.u64 t, %1; cvt.u32.u64 %0, t; }"
        : "=r"(a) : "l"(p));
    return a;
}
__device__ __forceinline__ uint32_t elect1() {
    uint32_t p;
    asm volatile(
        "{\n\t.reg .pred p;\n\telect.sync _|p, 0xFFFFFFFF;\n\t"
        "selp.b32 %0, 1, 0, p;\n\t}" : "=r"(p));
    return p;
}
__device__ __forceinline__ uint32_t swz(uint32_t off) {
    return off ^ ((off >> 3) & 0x70);
}
__device__ __forceinline__ void cp16(uint32_t sdst, const void* gsrc) {
    asm volatile("cp.async.cg.shared.global [%0], [%1], 16;"
                 :: "r"(sdst), "l"(gsrc) : "memory");
}
__device__ __forceinline__ uint64_t mkdesc(uint32_t addr) {
    // SW128, version=1 (Blackwell), SBO=64, LBO=1, K-major
    return ((uint64_t)2 << 61) | ((uint64_t)1 << 46) | ((uint64_t)64 << 32)
         | ((uint64_t)1 << 16) | ((uint64_t)((addr >> 4) & 0x3FFF));
}
__device__ __forceinline__ void mbar_wait(uint32_t mbar, uint32_t parity) {
    asm volatile(
        "{\n\t.reg .pred P1;\n\t"
        "WAIT_%=:\n\t"
        "mbarrier.try_wait.parity.acquire.cta.shared::cta.b64 P1, [%0], %1, 0x989680;\n\t"
        "@P1 bra.uni DONE_%=;\n\t"
        "bra.uni WAIT_%=;\n\t"
        "DONE_%=:\n\t}"
        :: "r"(mbar), "r"(parity) : "memory");
}
__device__ __forceinline__ void mma_bf16_ss(uint32_t d, uint64_t ad, uint64_t bd,
                                            uint32_t idesc, uint32_t en) {
    asm volatile(
        "{\n\t.reg .pred p;\n\tsetp.ne.u32 p, %4, 0;\n\t"
        "tcgen05.mma.cta_group::1.kind::f16 [%0], %1, %2, %3, {%5, %5, %5, %5}, p;\n\t}"
        :: "r"(d), "l"(ad), "l"(bd), "r"(idesc), "r"(en), "r"(0u)
        : "memory");
}
#define LDTM_X32(r, addr) \
    asm volatile( \
        "tcgen05.ld.sync.aligned.32x32b.x32.b32 " \
        "{%0, %1, %2, %3, %4, %5, %6, %7, " \
        " %8, %9, %10, %11, %12, %13, %14, %15, " \
        " %16, %17, %18, %19, %20, %21, %22, %23, " \
        " %24, %25, %26, %27, %28, %29, %30, %31}, [%32];" \
        : "=r"((r)[0]),  "=r"((r)[1]),  "=r"((r)[2]),  "=r"((r)[3]), \
          "=r"((r)[4]),  "=r"((r)[5]),  "=r"((r)[6]),  "=r"((r)[7]), \
          "=r"((r)[8]),  "=r"((r)[9]),  "=r"((r)[10]), "=r"((r)[11]), \
          "=r"((r)[12]), "=r"((r)[13]), "=r"((r)[14]), "=r"((r)[15]), \
          "=r"((r)[16]), "=r"((r)[17]), "=r"((r)[18]), "=r"((r)[19]), \
          "=r"((r)[20]), "=r"((r)[21]), "=r"((r)[22]), "=r"((r)[23]), \
          "=r"((r)[24]), "=r"((r)[25]), "=r"((r)[26]), "=r"((r)[27]), \
          "=r"((r)[28]), "=r"((r)[29]), "=r"((r)[30]), "=r"((r)[31]) \
        : "r"(addr))

#define GT_IDESC ((1u << 4) | (1u << 7) | (1u << 10) \
                 | ((GT_N / 8) << 17) | ((GT_M / 16) << 24))
#endif  // HAS_TCGEN05

__global__ __launch_bounds__(128)
void gemm_tc(const __nv_bfloat16* __restrict__ Ah, const __nv_bfloat16* __restrict__ Al,
             const __nv_bfloat16* __restrict__ Bth, const __nv_bfloat16* __restrict__ Btl,
             const float* __restrict__ bias, float* __restrict__ C,
             int N, int K, float alpha, int relu)
{
#if HAS_TCGEN05
    extern __shared__ __align__(16) char dynsmem[];
    __shared__ uint32_t s_tmem;
    __shared__ __align__(8) uint64_t s_mbar[3];

    const int tid = threadIdx.x;
    const int wid = tid >> 5;
    const int lane = tid & 31;
    const int m0 = blockIdx.y * GT_M;
    const int n0 = blockIdx.x * GT_N;

    const uint32_t sbase = (s2u(dynsmem) + 1023) & ~1023u;
    const uint32_t mb0 = s2u(&s_mbar[0]);
    const uint32_t mb1 = s2u(&s_mbar[1]);
    const uint32_t mbf = s2u(&s_mbar[2]);

    if (tid == 0) {
        asm volatile("mbarrier.init.shared.b64 [%0], 1;" :: "r"(mb0) : "memory");
        asm volatile("mbarrier.init.shared.b64 [%0], 1;" :: "r"(mb1) : "memory");
        asm volatile("mbarrier.init.shared.b64 [%0], 1;" :: "r"(mbf) : "memory");
    }
    if (wid == 0) {
        asm volatile("tcgen05.alloc.cta_group::1.sync.aligned.shared::cta.b32 [%0], %1;"
                     :: "r"(s2u(&s_tmem)), "r"(512u) : "memory");
    }
    __syncthreads();
    const uint32_t tmem = s_tmem;
    if (wid == 0)
        asm volatile("tcgen05.relinquish_alloc_permit.cta_group::1.sync.aligned;");

    const int NC = K >> 6;
    const size_t Kb = (size_t)K * 2;

    const uint8_t* pAh = (const uint8_t*)Ah + (size_t)m0 * Kb;
    const uint8_t* pAl = (const uint8_t*)Al + (size_t)m0 * Kb;
    const uint8_t* pBh = (const uint8_t*)Bth + (size_t)n0 * Kb;
    const uint8_t* pBl = (const uint8_t*)Btl + (size_t)n0 * Kb;

    auto load_chunk = [&](int s, int c) {
        const uint32_t st = sbase + s * STAGE_BYTES;
        const uint32_t aH = st;
        const uint32_t aL = st + STAGE_A;
        const uint32_t bH = st + 2 * STAGE_A;
        const uint32_t bL = st + 2 * STAGE_A + STAGE_B;
        const size_t koff = (size_t)c * 128;       // 64 bf16 = 128 B
        #pragma unroll
        for (int i = 0; i < 8; i++) {
            int idx = tid + i * 128;
            int row = idx >> 3;
            int cb = (idx & 7) * 16;
            uint32_t so = swz((uint32_t)(row * 128 + cb));
            size_t go = (size_t)row * Kb + koff + cb;
            cp16(aH + so, pAh + go);
            cp16(aL + so, pAl + go);
        }
        #pragma unroll
        for (int i = 0; i < 16; i++) {
            int idx = tid + i * 128;
            int row = idx >> 3;
            int cb = (idx & 7) * 16;
            uint32_t so = swz((uint32_t)(row * 128 + cb));
            size_t go = (size_t)row * Kb + koff + cb;
            cp16(bH + so, pBh + go);
            cp16(bL + so, pBl + go);
        }
        asm volatile("cp.async.commit_group;" ::: "memory");
    };

    load_chunk(0, 0);
    load_chunk(1, 1);

    int ph0 = 0, ph1 = 0;
    for (int c = 0; c < NC; c++) {
        const int s = c & 1;
        if (c < NC - 1)
            asm volatile("cp.async.wait_group 1;" ::: "memory");
        else
            asm volatile("cp.async.wait_group 0;" ::: "memory");
        __syncthreads();
        asm volatile("fence.proxy.async.shared::cta;" ::: "memory");

        if (wid == 0 && elect1()) {
            const uint32_t st = sbase + s * STAGE_BYTES;
            const uint64_t adh = mkdesc(st);
            const uint64_t adl = mkdesc(st + STAGE_A);
            const uint64_t bdh = mkdesc(st + 2 * STAGE_A);
            const uint64_t bdl = mkdesc(st + 2 * STAGE_A + STAGE_B);
            #pragma unroll
            for (int ks = 0; ks < 4; ks++) {
                mma_bf16_ss(tmem, adh + ks * 2, bdh + ks * 2, GT_IDESC,
                            (uint32_t)((c | ks) != 0));
                mma_bf16_ss(tmem, adh + ks * 2, bdl + ks * 2, GT_IDESC, 1u);
                mma_bf16_ss(tmem, adl + ks * 2, bdh + ks * 2, GT_IDESC, 1u);
            }
            asm volatile(
                "tcgen05.commit.cta_group::1.mbarrier::arrive::one.shared::cluster.b64 [%0];"
                :: "r"(s ? mb1 : mb0) : "memory");
        }

        if (c + 2 < NC) {
            if (s == 0) { mbar_wait(mb0, ph0); ph0 ^= 1; }
            else        { mbar_wait(mb1, ph1); ph1 ^= 1; }
            load_chunk(s, c + 2);
        }
    }

    if (wid == 0 && elect1()) {
        asm volatile(
            "tcgen05.commit.cta_group::1.mbarrier::arrive::one.shared::cluster.b64 [%0];"
            :: "r"(mbf) : "memory");
    }
    mbar_wait(mbf, 0);
    asm volatile("tcgen05.fence::after_thread_sync;" ::: "memory");

    // epilogue: each warp reads its 32-row subpartition, 32 cols at a time
    const int row = m0 + wid * 32 + lane;
    float* Crow = C + (size_t)row * N + n0;
    #pragma unroll
    for (int nb = 0; nb < GT_N / 32; nb++) {
        uint32_t r[32];
        LDTM_X32(r, tmem + nb * 32);
        asm volatile("tcgen05.wait::ld.sync.aligned;" ::: "memory");
        const float* bb = bias + n0 + nb * 32;
        #pragma unroll
        for (int c4 = 0; c4 < 32; c4 += 4) {
            float4 o;
            o.x = alpha * (__uint_as_float(r[c4 + 0]) + bb[c4 + 0]);
            o.y = alpha * (__uint_as_float(r[c4 + 1]) + bb[c4 + 1]);
            o.z = alpha * (__uint_as_float(r[c4 + 2]) + bb[c4 + 2]);
            o.w = alpha * (__uint_as_float(r[c4 + 3]) + bb[c4 + 3]);
            if (relu) {
                o.x = fmaxf(o.x, 0.f); o.y = fmaxf(o.y, 0.f);
                o.z = fmaxf(o.z, 0.f); o.w = fmaxf(o.w, 0.f);
            }
            *(float4*)(Crow + nb * 32 + c4) = o;
        }
    }
    __syncthreads();
    if (wid == 0)
        asm volatile("tcgen05.dealloc.cta_group::1.sync.aligned.b32 %0, %1;"
                     :: "r"(tmem), "r"(512u));
#endif  // HAS_TCGEN05
}

// -------------------- mma.sync fallback GEMM (R4, known-correct) -----------
#define SMS 40

__device__ __forceinline__ void mma16816(float* c, const uint32_t* a, const uint32_t* b)
{
    asm volatile(
        "mma.sync.aligned.m16n8k16.row.col.f32.bf16.bf16.f32 "
        "{%0,%1,%2,%3}, {%4,%5,%6,%7}, {%8,%9}, {%0,%1,%2,%3};"
        : "+f"(c[0]), "+f"(c[1]), "+f"(c[2]), "+f"(c[3])
        : "r"(a[0]), "r"(a[1]), "r"(a[2]), "r"(a[3]), "r"(b[0]), "r"(b[1]));
}

__global__ __launch_bounds__(256) void gemm3x(
    const __nv_bfloat16* __restrict__ Ah, const __nv_bfloat16* __restrict__ Al,
    const __nv_bfloat16* __restrict__ Bth, const __nv_bfloat16* __restrict__ Btl,
    const float* __restrict__ bias, float* __restrict__ C,
    int M, int N, int K, float alpha, int relu)
{
    __shared__ __align__(16) __nv_bfloat16 As_h[128 * SMS];
    __shared__ __align__(16) __nv_bfloat16 As_l[128 * SMS];
    __shared__ __align__(16) __nv_bfloat16 Bs_h[128 * SMS];
    __shared__ __align__(16) __nv_bfloat16 Bs_l[128 * SMS];

    const int tid = threadIdx.x;
    const int warp = tid >> 5;
    const int lane = tid & 31;
    const int g = lane >> 2;
    const int t2 = (lane & 3) * 2;
    const int wm = warp >> 1;
    const int wn = warp & 1;
    const int m0 = blockIdx.y * 128;
    const int n0 = blockIdx.x * 128;

    float acc[2][8][4];
    #pragma unroll
    for (int i = 0; i < 2; i++)
        #pragma unroll
        for (int j = 0; j < 8; j++)
            #pragma unroll
            for (int c = 0; c < 4; c++) acc[i][j][c] = 0.f;

    for (int k0 = 0; k0 < K; k0 += 32) {
        #pragma unroll
        for (int r = 0; r < 2; r++) {
            int c = tid + r * 256;
            int row = c >> 2;
            int qt = (c & 3) * 8;
            size_t ga = (size_t)(m0 + row) * K + k0 + qt;
            size_t gb = (size_t)(n0 + row) * K + k0 + qt;
            *(uint4*)&As_h[row * SMS + qt] = *(const uint4*)&Ah[ga];
            *(uint4*)&As_l[row * SMS + qt] = *(const uint4*)&Al[ga];
            *(uint4*)&Bs_h[row * SMS + qt] = *(const uint4*)&Bth[gb];
            *(uint4*)&Bs_l[row * SMS + qt] = *(const uint4*)&Btl[gb];
        }
        __syncthreads();

        #pragma unroll
        for (int kk = 0; kk < 32; kk += 16) {
            uint32_t bh[8][2], bl[8][2];
            #pragma unroll
            for (int ns = 0; ns < 8; ns++) {
                int n = wn * 64 + ns * 8 + g;
                bh[ns][0] = *(const uint32_t*)&Bs_h[n * SMS + kk + t2];
                bh[ns][1] = *(const uint32_t*)&Bs_h[n * SMS + kk + t2 + 8];
                bl[ns][0] = *(const uint32_t*)&Bs_l[n * SMS + kk + t2];
                bl[ns][1] = *(const uint32_t*)&Bs_l[n * SMS + kk + t2 + 8];
            }
            #pragma unroll
            for (int ms = 0; ms < 2; ms++) {
                int r0 = wm * 32 + ms * 16 + g;
                uint32_t ah[4], al[4];
                ah[0] = *(const uint32_t*)&As_h[r0 * SMS + kk + t2];
                ah[1] = *(const uint32_t*)&As_h[(r0 + 8) * SMS + kk + t2];
                ah[2] = *(const uint32_t*)&As_h[r0 * SMS + kk + t2 + 8];
                ah[3] = *(const uint32_t*)&As_h[(r0 + 8) * SMS + kk + t2 + 8];
                al[0] = *(const uint32_t*)&As_l[r0 * SMS + kk + t2];
                al[1] = *(const uint32_t*)&As_l[(r0 + 8) * SMS + kk + t2];
                al[2] = *(const uint32_t*)&As_l[r0 * SMS + kk + t2 + 8];
                al[3] = *(const uint32_t*)&As_l[(r0 + 8) * SMS + kk + t2 + 8];
                #pragma unroll
                for (int ns = 0; ns < 8; ns++) {
                    mma16816(acc[ms][ns], ah, bh[ns]);
                    mma16816(acc[ms][ns], ah, bl[ns]);
                    mma16816(acc[ms][ns], al, bh[ns]);
                }
            }
        }
        __syncthreads();
    }

    #pragma unroll
    for (int ms = 0; ms < 2; ms++) {
        #pragma unroll
        for (int ns = 0; ns < 8; ns++) {
            int row0 = m0 + wm * 32 + ms * 16 + g;
            int col  = n0 + wn * 64 + ns * 8 + t2;
            float b0 = bias[col], b1 = bias[col + 1];
            float v0 = alpha * (acc[ms][ns][0] + b0);
            float v1 = alpha * (acc[ms][ns][1] + b1);
            float v2 = alpha * (acc[ms][ns][2] + b0);
            float v3 = alpha * (acc[ms][ns][3] + b1);
            if (relu) {
                v0 = fmaxf(v0, 0.f); v1 = fmaxf(v1, 0.f);
                v2 = fmaxf(v2, 0.f); v3 = fmaxf(v3, 0.f);
            }
            *(float2*)&C[(size_t)row0 * N + col] = make_float2(v0, v1);
            *(float2*)&C[(size_t)(row0 + 8) * N + col] = make_float2(v2, v3);
        }
    }
}

// -------------------- block reductions (256 threads) -----------------------
__device__ __forceinline__ float block_sum256(float v, float* red) {
    #pragma unroll
    for (int o = 16; o; o >>= 1) v += __shfl_xor_sync(0xffffffffu, v, o);
    int t = threadIdx.x;
    if ((t & 31) == 0) red[t >> 5] = v;
    __syncthreads();
    float r = (t < 8) ? red[t] : 0.f;
    if (t < 32) {
        #pragma unroll
        for (int o = 4; o; o >>= 1) r += __shfl_xor_sync(0xffffffffu, r, o);
        if (t == 0) red[0] = r;
    }
    __syncthreads();
    r = red[0];
    __syncthreads();
    return r;
}

__device__ __forceinline__ float block_max256(float v, float* red) {
    #pragma unroll
    for (int o = 16; o; o >>= 1) v = fmaxf(v, __shfl_xor_sync(0xffffffffu, v, o));
    int t = threadIdx.x;
    if ((t & 31) == 0) red[t >> 5] = v;
    __syncthreads();
    float r = (t < 8) ? red[t] : -3.4e38f;
    if (t < 32) {
        #pragma unroll
        for (int o = 4; o; o >>= 1) r = fmaxf(r, __shfl_xor_sync(0xffffffffu, r, o));
        if (t == 0) red[0] = r;
    }
    __syncthreads();
    r = red[0];
    __syncthreads();
    return r;
}

// -------------------- weight split + transpose -----------------------------
__global__ __launch_bounds__(256) void wsplit_t(
    const float* __restrict__ W, __nv_bfloat16* __restrict__ Th,
    __nv_bfloat16* __restrict__ Tl, int K, int N)
{
    __shared__ float tile[32][33];
    const int l = blockIdx.z;
    const float* Wl = W + (size_t)l * K * N;
    __nv_bfloat16* Thl = Th + (size_t)l * K * N;
    __nv_bfloat16* Tll = Tl + (size_t)l * K * N;
    const int n0 = blockIdx.x * 32, k0 = blockIdx.y * 32;
    const int tx = threadIdx.x & 31, ty = threadIdx.x >> 5;
    #pragma unroll
    for (int j = 0; j < 32; j += 8)
        tile[ty + j][tx] = Wl[(size_t)(k0 + ty + j) * N + n0 + tx];
    __syncthreads();
    #pragma unroll
    for (int j = 0; j < 32; j += 8) {
        float v = tile[tx][ty + j];
        __nv_bfloat16 h = __float2bfloat16(v);
        float lo = v - __bfloat162float(h);
        size_t o = (size_t)(n0 + ty + j) * K + k0 + tx;
        Thl[o] = h;
        Tll[o] = __float2bfloat16(lo);
    }
}

// -------------------- activation split -------------------------------------
__global__ __launch_bounds__(256) void asplit(
    const float* __restrict__ x, __nv_bfloat16* __restrict__ hh,
    __nv_bfloat16* __restrict__ ll)
{
    size_t i = ((size_t)blockIdx.x * 256 + threadIdx.x) * 4;
    float4 v = *(const float4*)(x + i);
    __nv_bfloat16 h0 = __float2bfloat16(v.x);
    __nv_bfloat16 h1 = __float2bfloat16(v.y);
    __nv_bfloat16 h2 = __float2bfloat16(v.z);
    __nv_bfloat16 h3 = __float2bfloat16(v.w);
    __nv_bfloat162* ph = (__nv_bfloat162*)(hh + i);
    ph[0] = __nv_bfloat162(h0, h1);
    ph[1] = __nv_bfloat162(h2, h3);
    __nv_bfloat162* pl = (__nv_bfloat162*)(ll + i);
    pl[0] = __nv_bfloat162(__float2bfloat16(v.x - __bfloat162float(h0)),
                           __float2bfloat16(v.y - __bfloat162float(h1)));
    pl[1] = __nv_bfloat162(__float2bfloat16(v.z - __bfloat162float(h2)),
                           __float2bfloat16(v.w - __bfloat162float(h3)));
}

// -------------------- fused attention: one block per (q row, b, h) ---------
__global__ __launch_bounds__(256) void attn_fused(
    const float* __restrict__ gq, const float* __restrict__ gk,
    const float* __restrict__ gv, float* __restrict__ gu)
{
    __shared__ float qrow[HEAD_DIM];
    __shared__ float P[SEQ];
    __shared__ float red[32];
    __shared__ float Uacc[4][HEAD_DIM];

    const int q  = blockIdx.x;
    const int bh = blockIdx.y;
    const int b  = bh >> 4;
    const int h  = bh & 15;
    const int t  = threadIdx.x;

    const float* qb = gq + ((size_t)b * SEQ + q) * EMBED + h * HEAD_DIM;
    const float* kb = gk + (size_t)b * SEQ * EMBED + h * HEAD_DIM;
    const float* vb = gv + (size_t)b * SEQ * EMBED + h * HEAD_DIM;

    if (t < 16) ((float4*)qrow)[t] = ((const float4*)qb)[t];
    __syncthreads();

    float s[4];
    #pragma unroll
    for (int j = 0; j < 4; j++) {
        const float* krow = kb + (size_t)(t + j * 256) * EMBED;
        float acc = 0.f;
        #pragma unroll
        for (int d4 = 0; d4 < 16; d4++) {
            float4 kv = ((const float4*)krow)[d4];
            acc = fmaf(qrow[d4 * 4 + 0], kv.x, acc);
            acc = fmaf(qrow[d4 * 4 + 1], kv.y, acc);
            acc = fmaf(qrow[d4 * 4 + 2], kv.z, acc);
            acc = fmaf(qrow[d4 * 4 + 3], kv.w, acc);
        }
        s[j] = acc;
    }

    float mx = fmaxf(fmaxf(s[0], s[1]), fmaxf(s[2], s[3]));
    mx = block_max256(mx, red);
    float sum = 0.f;
    #pragma unroll
    for (int j = 0; j < 4; j++) { s[j] = __expf(s[j] - mx); sum += s[j]; }
    sum = block_sum256(sum, red);
    float inv = 1.f / sum;
    #pragma unroll
    for (int j = 0; j < 4; j++) P[t + j * 256] = s[j] * inv;
    __syncthreads();

    const int d = t & 63;
    const int slice = t >> 6;
    float u = 0.f;
    const int kbeg = slice * 256;
    #pragma unroll 4
    for (int k = kbeg; k < kbeg + 256; k++)
        u = fmaf(P[k], vb[(size_t)k * EMBED + d], u);
    Uacc[slice][d] = u;
    __syncthreads();

    if (t < HEAD_DIM) {
        float r2 = Uacc[0][t] + Uacc[1][t] + Uacc[2][t] + Uacc[3][t];
        gu[((size_t)b * SEQ + q) * EMBED + h * HEAD_DIM + t] = r2;
    }
}

// -------------------- residual + layernorm ---------------------------------
__global__ __launch_bounds__(256) void ln_residual(
    const float* __restrict__ a, const float* __restrict__ res,
    const float* __restrict__ sc, const float* __restrict__ bi,
    float* __restrict__ out)
{
    __shared__ float red[32];
    const size_t row = blockIdx.x;
    const int t = threadIdx.x;
    float4 a4 = ((const float4*)(a + row * EMBED))[t];
    float4 r4 = ((const float4*)(res + row * EMBED))[t];
    float4 v;
    v.x = a4.x + r4.x; v.y = a4.y + r4.y; v.z = a4.z + r4.z; v.w = a4.w + r4.w;
    float s = v.x + v.y + v.z + v.w;
    s = block_sum256(s, red);
    float mean = s * (1.f / EMBED);
    v.x -= mean; v.y -= mean; v.z -= mean; v.w -= mean;
    float sq = v.x * v.x + v.y * v.y + v.z * v.z + v.w * v.w;
    sq = block_sum256(sq, red);
    float inv = rsqrtf(sq * (1.f / EMBED) + EPS_LN);
    float4 s4 = ((const float4*)sc)[t];
    float4 b4 = ((const float4*)bi)[t];
    float4 o;
    o.x = v.x * inv * s4.x + b4.x;
    o.y = v.y * inv * s4.y + b4.y;
    o.z = v.z * inv * s4.z + b4.z;
    o.w = v.w * inv * s4.w + b4.w;
    ((float4*)(out + row * EMBED))[t] = o;
}

// -------------------- input identification ---------------------------------
struct Inputs {
    const float *queries, *Wq, *bq, *Wk, *bk, *Wv, *bv, *Wo, *bo;
    const float *l1s, *l1b, *l2s, *l2b, *W1, *b1, *W2, *b2;
};

static void map_inputs(void* const* d_in, const int* in_sizes, Inputs* I)
{
    const int SZ_Q = MTOT * EMBED;
    const int SZ_W = NUM_LAYERS * EMBED * MLPDIM;
    const int SZ_B1 = NUM_LAYERS * MLPDIM;
    const int SZ_V = NUM_LAYERS * EMBED;

    static const int dict_pat[17] = {SZ_Q,SZ_Q,SZ_V,SZ_Q,SZ_V,SZ_Q,SZ_V,SZ_Q,
                                     SZ_V,SZ_V,SZ_V,SZ_V,SZ_V,SZ_W,SZ_B1,SZ_W,SZ_V};
    static const int alpha_pat[17] = {SZ_W,SZ_W,SZ_Q,SZ_Q,SZ_Q,SZ_Q,SZ_B1,SZ_V,
                                      SZ_V,SZ_V,SZ_V,SZ_V,SZ_V,SZ_V,SZ_V,SZ_V,SZ_Q};
    bool is_dict = true, is_alpha = true;
    for (int i = 0; i < 17; i++) {
        if (in_sizes[i] != dict_pat[i])  is_dict = false;
        if (in_sizes[i] != alpha_pat[i]) is_alpha = false;
    }
    const float** p = (const float**)d_in;
    if (is_alpha) {
        I->W1 = p[0];  I->W2 = p[1];  I->Wk = p[2];  I->Wo = p[3];
        I->Wq = p[4];  I->Wv = p[5];  I->b1 = p[6];  I->b2 = p[7];
        I->bk = p[8];  I->bo = p[9];  I->bq = p[10]; I->bv = p[11];
        I->l1b = p[12];I->l1s = p[13];I->l2b = p[14];I->l2s = p[15];
        I->queries = p[16];
    } else if (is_dict) {
        I->queries = p[0];  I->Wq = p[1];  I->bq = p[2];  I->Wk = p[3];
        I->bk = p[4];       I->Wv = p[5];  I->bv = p[6];  I->Wo = p[7];
        I->bo = p[8];       I->l1s = p[9]; I->l1b = p[10];I->l2s = p[11];
        I->l2b = p[12];     I->W1 = p[13]; I->b1 = p[14]; I->W2 = p[15];
        I->b2 = p[16];
    } else {
        const float* cq[8]; int nq = 0;
        const float* cw[4]; int nw = 0;
        const float* cv[12]; int nv = 0;
        const float* cb1 = 0;
        for (int i = 0; i < 17; i++) {
            if (in_sizes[i] == SZ_Q && nq < 8) cq[nq++] = p[i];
            else if (in_sizes[i] == SZ_W && nw < 4) cw[nw++] = p[i];
            else if (in_sizes[i] == SZ_B1) cb1 = p[i];
            else if (nv < 12) cv[nv++] = p[i];
        }
        I->queries = cq[0]; I->Wq = cq[1]; I->Wk = cq[2]; I->Wv = cq[3]; I->Wo = cq[4];
        I->W1 = cw[0]; I->W2 = cw[1]; I->b1 = cb1;
        I->bq = cv[0]; I->bk = cv[1]; I->bv = cv[2]; I->bo = cv[3];
        I->l1s = cv[4]; I->l1b = cv[5]; I->l2s = cv[6]; I->l2b = cv[7]; I->b2 = cv[8];
    }
}

// -------------------- host orchestration -----------------------------------
static float* sym_addr_f(const void* sym) {
    void* pv = 0;
    cudaGetSymbolAddress(&pv, sym);
    return (float*)pv;
}
static __nv_bfloat16* sym_addr_b(const void* sym) {
    void* pv = 0;
    cudaGetSymbolAddress(&pv, sym);
    return (__nv_bfloat16*)pv;
}

extern "C" void kernel_launch(void* const* d_in, const int* in_sizes, int n_in,
                              void* d_out, int out_size)
{
    Inputs I;
    map_inputs(d_in, in_sizes, &I);
    float* out = (float*)d_out;

    // Discriminate which gemm_tc body got loaded: the tcgen05 body uses many
    // registers; the gated-out stub uses almost none. Deterministic host query.
    int use_tc = 0;
    {
        cudaFuncAttributes fa;
        if (cudaFuncGetAttributes(&fa, gemm_tc) == cudaSuccess)
            use_tc = (fa.numRegs >= 40);
    }
    if (use_tc)
        cudaFuncSetAttribute(gemm_tc, cudaFuncAttributeMaxDynamicSharedMemorySize,
                             GEMM_SMEM);

    float* fbase = sym_addr_f(g_f);
    float* x = fbase + 0 * NSLAB;
    float* q = fbase + 1 * NSLAB;
    float* k = fbase + 2 * NSLAB;
    float* v = fbase + 3 * NSLAB;
    float* u = fbase + 4 * NSLAB;
    float* a = fbase + 5 * NSLAB;
    float* h = fbase + 6 * NSLAB;
    float* z = fbase + 7 * NSLAB;
    float* m = fbase + 8 * NSLAB;

    __nv_bfloat16 *wq_h = sym_addr_b(g_wq_h), *wq_l = sym_addr_b(g_wq_l);
    __nv_bfloat16 *wk_h = sym_addr_b(g_wk_h), *wk_l = sym_addr_b(g_wk_l);
    __nv_bfloat16 *wv_h = sym_addr_b(g_wv_h), *wv_l = sym_addr_b(g_wv_l);
    __nv_bfloat16 *wo_h = sym_addr_b(g_wo_h), *wo_l = sym_addr_b(g_wo_l);
    __nv_bfloat16 *w1_h = sym_addr_b(g_w1_h), *w1_l = sym_addr_b(g_w1_l);
    __nv_bfloat16 *w2_h = sym_addr_b(g_w2_h), *w2_l = sym_addr_b(g_w2_l);
    __nv_bfloat16 *ah = sym_addr_b(g_ah), *al = sym_addr_b(g_al);

    dim3 tgrid_q(EMBED / 32, EMBED / 32, NUM_LAYERS);
    wsplit_t<<<tgrid_q, 256>>>(I.Wq, wq_h, wq_l, EMBED, EMBED);
    wsplit_t<<<tgrid_q, 256>>>(I.Wk, wk_h, wk_l, EMBED, EMBED);
    wsplit_t<<<tgrid_q, 256>>>(I.Wv, wv_h, wv_l, EMBED, EMBED);
    wsplit_t<<<tgrid_q, 256>>>(I.Wo, wo_h, wo_l, EMBED, EMBED);
    wsplit_t<<<dim3(MLPDIM / 32, EMBED / 32, NUM_LAYERS), 256>>>(
        I.W1, w1_h, w1_l, EMBED, MLPDIM);
    wsplit_t<<<dim3(EMBED / 32, MLPDIM / 32, NUM_LAYERS), 256>>>(
        I.W2, w2_h, w2_l, MLPDIM, EMBED);

    cudaMemcpyAsync(x, I.queries, NSLAB * sizeof(float), cudaMemcpyDeviceToDevice, 0);

    const float qscale = 1.f / sqrtf((float)HEAD_DIM);
    const int AS_E = (int)(NSLAB / 1024);
    const int AS_M = (int)((size_t)MTOT * MLPDIM / 1024);

    auto GEMM = [&](const __nv_bfloat16* Ahp, const __nv_bfloat16* Alp,
                    const __nv_bfloat16* Bhp, const __nv_bfloat16* Blp,
                    const float* bias, float* Cp, int N, int K,
                    float alpha, int relu) {
        if (use_tc)
            gemm_tc<<<dim3(N / GT_N, MTOT / GT_M), 128, GEMM_SMEM>>>(
                Ahp, Alp, Bhp, Blp, bias, Cp, N, K, alpha, relu);
        else
            gemm3x<<<dim3(N / 128, MTOT / 128), 256>>>(
                Ahp, Alp, Bhp, Blp, bias, Cp, MTOT, N, K, alpha, relu);
    };

    for (int l = 0; l < NUM_LAYERS; l++) {
        size_t woq = (size_t)l * EMBED * EMBED;
        size_t wom = (size_t)l * EMBED * MLPDIM;
        const float* bq_l = I.bq + (size_t)l * EMBED;
        const float* bk_l = I.bk + (size_t)l * EMBED;
        const float* bv_l = I.bv + (size_t)l * EMBED;
        const float* bo_l = I.bo + (size_t)l * EMBED;
        const float* b1_l = I.b1 + (size_t)l * MLPDIM;
        const float* b2_l = I.b2 + (size_t)l * EMBED;
        const float* l1s = I.l1s + (size_t)l * EMBED;
        const float* l1b = I.l1b + (size_t)l * EMBED;
        const float* l2s = I.l2s + (size_t)l * EMBED;
        const float* l2b = I.l2b + (size_t)l * EMBED;

        asplit<<<AS_E, 256>>>(x, ah, al);
        GEMM(ah, al, wq_h + woq, wq_l + woq, bq_l, q, EMBED, EMBED, qscale, 0);
        GEMM(ah, al, wk_h + woq, wk_l + woq, bk_l, k, EMBED, EMBED, 1.f, 0);
        GEMM(ah, al, wv_h + woq, wv_l + woq, bv_l, v, EMBED, EMBED, 1.f, 0);

        attn_fused<<<dim3(SEQ, BATCH * HEADS), 256>>>(q, k, v, u);

        asplit<<<AS_E, 256>>>(u, ah, al);
        GEMM(ah, al, wo_h + woq, wo_l + woq, bo_l, a, EMBED, EMBED, 1.f, 0);
        ln_residual<<<MTOT, 256>>>(a, x, l1s, l1b, h);

        asplit<<<AS_E, 256>>>(h, ah, al);
        GEMM(ah, al, w1_h + wom, w1_l + wom, b1_l, m, MLPDIM, EMBED, 1.f, 1);

        asplit<<<AS_M, 256>>>(m, ah, al);
        GEMM(ah, al, w2_h + wom, w2_l + wom, b2_l, z, EMBED, MLPDIM, 1.f, 0);
        ln_residual<<<MTOT, 256>>>(z, h, l2s, l2b, x);
    }

    cudaMemcpyAsync(out, x, NSLAB * sizeof(float), cudaMemcpyDeviceToDevice, 0);
}